// round 1
// baseline (speedup 1.0000x reference)
#include <cuda_runtime.h>
#include <math.h>

// ---------------- problem constants ----------------
#define NN     20000
#define EE     160000
#define FEE    500000
#define INF_   128
#define HC     64
#define HEADS  4
#define HEADC  16
#define DV     16
#define KHOP   3
#define NUMT   128
#define CSTADD 1e-5f
#define MSL    1024   // HEADS*HEADC*DV floats of M per node

// ---------------- scratch (static device globals; no allocs) ----------------
__device__ float g_M[2][NN * MSL];      // ping-pong state matrices, 2 x 81.9MB
__device__ float g_Kf[2][NN * HC];
__device__ float g_Q[NN * HC];
__device__ float g_hid[NN * HC];        // per-head hidden accumulator [N,4,16]
__device__ float g_hid16[NN * 16];      // after Wo projection
__device__ float g_temb[NUMT * HC];     // timestep-embedding MLP table
__device__ int   g_deg[NN];
__device__ int   g_off[NN + 1];
__device__ int   g_cur[NN];
__device__ int   g_crow[EE];            // CSR (by dest): source node per edge
__device__ float g_cnorm[EE];           // edge weight (1/deg[row])

// ---------------- helpers ----------------
__device__ __forceinline__ float oneelu(float x) {
    return x > 0.f ? 1.f + x : expf(x);
}
__device__ __forceinline__ float silu(float x) {
    return x / (1.f + expf(-x));
}

// ---------------- 1. zero counters ----------------
__global__ void k_zero() {
    int i = blockIdx.x * blockDim.x + threadIdx.x;
    if (i < NN) { g_deg[i] = 0; g_cur[i] = 0; }
}

// ---------------- 2. in-degree (over col) ----------------
__global__ void k_deg(const int* __restrict__ ei) {
    int e = blockIdx.x * blockDim.x + threadIdx.x;
    if (e < EE) atomicAdd(&g_deg[ei[EE + e]], 1);
}

// ---------------- 3. exclusive scan of deg -> off (single block) ----------------
__global__ void k_scan() {
    __shared__ int sums[1024];
    const int CH = 20;                       // 1024*20 = 20480 >= NN
    int t = threadIdx.x;
    int start = t * CH;
    int local[CH];
    int s = 0;
    #pragma unroll
    for (int i = 0; i < CH; i++) {
        int idx = start + i;
        int v = (idx < NN) ? g_deg[idx] : 0;
        local[i] = s;
        s += v;
    }
    sums[t] = s;
    __syncthreads();
    for (int d = 1; d < 1024; d <<= 1) {
        int v = (t >= d) ? sums[t - d] : 0;
        __syncthreads();
        sums[t] += v;
        __syncthreads();
    }
    int base = (t > 0) ? sums[t - 1] : 0;
    #pragma unroll
    for (int i = 0; i < CH; i++) {
        int idx = start + i;
        if (idx < NN) g_off[idx] = base + local[i];
    }
    if (t == 1023) g_off[NN] = sums[1023];
}

// ---------------- 4. fill CSR (+ per-edge norm) ----------------
__global__ void k_csr(const int* __restrict__ ei) {
    int e = blockIdx.x * blockDim.x + threadIdx.x;
    if (e >= EE) return;
    int r = ei[e];            // row (source)
    int c = ei[EE + e];       // col (dest)
    int pos = atomicAdd(&g_cur[c], 1);
    int idx = g_off[c] + pos;
    g_crow[idx] = r;
    int dr = g_deg[r];
    g_cnorm[idx] = (dr > 0) ? (1.f / (float)dr) : 0.f;
}

// ---------------- 5. timestep embedding MLP table (128 rows) ----------------
__global__ void k_temb(const float* __restrict__ Wt1, const float* __restrict__ bt1,
                       const float* __restrict__ Wt2, const float* __restrict__ bt2) {
    __shared__ float emb[HC];
    __shared__ float t1[4 * HC];
    int tb = blockIdx.x;                 // timestep value 0..127
    int t = threadIdx.x;                 // 256 threads
    if (t < 32) {
        float tt = (float)tb * (4000.0f / (float)NUMT);
        float f = expf(-logf(10000.0f) / 31.0f * (float)t);
        float a = tt * f;
        emb[t] = sinf(a);
        emb[32 + t] = cosf(a);
    }
    __syncthreads();
    // t1 = silu(emb @ Wt1 + bt1), Wt1 [64,256]
    {
        float acc = bt1[t];
        #pragma unroll 8
        for (int k = 0; k < HC; k++) acc += emb[k] * Wt1[k * 256 + t];
        t1[t] = silu(acc);
    }
    __syncthreads();
    if (t < HC) {
        float acc = bt2[t];
        #pragma unroll 8
        for (int k = 0; k < 256; k++) acc += t1[k] * Wt2[k * HC + t];
        g_temb[tb * HC + t] = acc;
    }
}

// ---------------- 6. per-node features: h, Q, K, V, M, hidden0 ----------------
// 8 warps/block, each warp handles 4 nodes. grid = NN/32 = 625 blocks.
__global__ __launch_bounds__(256) void k_feat(
    const float* __restrict__ x, const int* __restrict__ tsteps,
    const float* __restrict__ Wi, const float* __restrict__ bi,
    const float* __restrict__ WQ, const float* __restrict__ bQ,
    const float* __restrict__ WK, const float* __restrict__ bK,
    const float* __restrict__ WV, const float* __restrict__ bV,
    const float* __restrict__ hopwise)
{
    __shared__ float sh[8][1280];        // per warp: xs[512] hs[256] ks[256] vs[256]
    int wl = threadIdx.x >> 5, l = threadIdx.x & 31;
    float* xs = sh[wl];
    float* hs = xs + 512;
    float* ks = hs + 256;
    float* vs = ks + 256;
    int nb = (blockIdx.x * 8 + wl) * 4;  // first of 4 nodes
    float hw0 = hopwise[0];

    #pragma unroll
    for (int nn = 0; nn < 4; nn++) {
        int n = nb + nn;
        #pragma unroll
        for (int r = 0; r < 4; r++)
            xs[nn * 128 + l + 32 * r] = x[n * 128 + l + 32 * r];
    }
    __syncwarp();

    int c0 = l, c1 = l + 32;
    float a0[4], a1[4];
    #pragma unroll
    for (int nn = 0; nn < 4; nn++) {
        int n = nb + nn;
        int tt = tsteps[n];
        a0[nn] = bi[c0] + g_temb[tt * HC + c0];
        a1[nn] = bi[c1] + g_temb[tt * HC + c1];
    }
    #pragma unroll 4
    for (int k = 0; k < 128; k++) {
        float w0 = Wi[k * HC + c0];
        float w1 = Wi[k * HC + c1];
        #pragma unroll
        for (int nn = 0; nn < 4; nn++) {
            float xv = xs[nn * 128 + k];
            a0[nn] += xv * w0;
            a1[nn] += xv * w1;
        }
    }
    #pragma unroll
    for (int nn = 0; nn < 4; nn++) {
        hs[nn * 64 + c0] = fmaxf(a0[nn], 0.f);
        hs[nn * 64 + c1] = fmaxf(a1[nn], 0.f);
    }
    __syncwarp();

    float q0[4], q1[4], kk0[4], kk1[4], v0[4], v1[4];
    #pragma unroll
    for (int nn = 0; nn < 4; nn++) {
        q0[nn] = bQ[c0]; q1[nn] = bQ[c1];
        kk0[nn] = bK[c0]; kk1[nn] = bK[c1];
        v0[nn] = bV[c0]; v1[nn] = bV[c1];
    }
    #pragma unroll 4
    for (int k = 0; k < 64; k++) {
        float wq0 = WQ[k * HC + c0], wq1 = WQ[k * HC + c1];
        float wk0 = WK[k * HC + c0], wk1 = WK[k * HC + c1];
        float wv0 = WV[k * HC + c0], wv1 = WV[k * HC + c1];
        #pragma unroll
        for (int nn = 0; nn < 4; nn++) {
            float hv = hs[nn * 64 + k];
            q0[nn] += hv * wq0; q1[nn] += hv * wq1;
            kk0[nn] += hv * wk0; kk1[nn] += hv * wk1;
            v0[nn] += hv * wv0; v1[nn] += hv * wv1;
        }
    }
    #pragma unroll
    for (int nn = 0; nn < 4; nn++) {
        int n = nb + nn;
        float Qa = oneelu(q0[nn]), Qb = oneelu(q1[nn]);
        g_Q[n * HC + c0] = Qa; g_Q[n * HC + c1] = Qb;
        float Ka = oneelu(kk0[nn]), Kb = oneelu(kk1[nn]);
        g_Kf[0][n * HC + c0] = Ka; g_Kf[0][n * HC + c1] = Kb;
        ks[nn * 64 + c0] = Ka; ks[nn * 64 + c1] = Kb;
        vs[nn * 64 + c0] = v0[nn]; vs[nn * 64 + c1] = v1[nn];
        g_hid[n * HC + c0] = v0[nn] * hw0;
        g_hid[n * HC + c1] = v1[nn] * hw0;
    }
    __syncwarp();

    // M[n,h,i,j] = K[h,i] * V[h,j]  (flat f = h*256 + i*16 + j)
    #pragma unroll
    for (int nn = 0; nn < 4; nn++) {
        int n = nb + nn;
        float4* Mp = (float4*)(g_M[0] + (size_t)n * MSL);
        #pragma unroll
        for (int p = 0; p < 8; p++) {
            int f = p * 128 + l * 4;
            int hd = f >> 8;
            int rem = f & 255;
            int i = rem >> 4;
            int j = rem & 15;
            float kv = ks[nn * 64 + hd * 16 + i];
            float4 v4 = *(float4*)(vs + nn * 64 + hd * 16 + j);
            float4 m;
            m.x = kv * v4.x; m.y = kv * v4.y; m.z = kv * v4.z; m.w = kv * v4.w;
            Mp[p * 32 + l] = m;
        }
    }
}

// ---------------- 7. one propagation hop (fused: propagate M/Kf + H,C + hidden) ----
// warp per (node, head). grid = NN*4/8 = 10000 blocks of 256 threads.
__global__ __launch_bounds__(256) void k_hop(
    const float* __restrict__ Min, float* __restrict__ Mout,
    const float* __restrict__ Kin, float* __restrict__ Kout,
    const float* __restrict__ hopwise, const float* __restrict__ headwise,
    int hop)
{
    int w = blockIdx.x * 8 + (threadIdx.x >> 5);
    int l = threadIdx.x & 31;
    int n = w >> 2;
    int hd = w & 3;

    int s = g_off[n], e = g_off[n + 1];
    float4 m0 = make_float4(0.f, 0.f, 0.f, 0.f);
    float4 m1 = m0;
    float kf = 0.f;
    int moff = hd * 256 + l * 4;     // coalesced: m0 -> flats [4l..4l+3], m1 -> +128

    for (int k = s; k < e; k++) {
        int r = g_crow[k];
        float wt = g_cnorm[k];
        const float4* p = (const float4*)(Min + (size_t)r * MSL + moff);
        float4 a = p[0];
        float4 b = p[32];
        m0.x += wt * a.x; m0.y += wt * a.y; m0.z += wt * a.z; m0.w += wt * a.w;
        m1.x += wt * b.x; m1.y += wt * b.y; m1.z += wt * b.z; m1.w += wt * b.w;
        if (l < 16) kf += wt * Kin[r * HC + hd * 16 + l];
    }

    float4* q = (float4*)(Mout + (size_t)n * MSL + moff);
    q[0] = m0;
    q[32] = m1;
    if (l < 16) Kout[n * HC + hd * 16 + l] = kf;

    // H[j] = sum_i Q[i]*M[i,j] ; lane holds i0=l>>2 (m0) and i0+8 (m1), j=(l&3)*4+q
    int i0 = l >> 2;
    float qlo = g_Q[n * HC + hd * 16 + i0];
    float qhi = g_Q[n * HC + hd * 16 + 8 + i0];
    float p0 = qlo * m0.x + qhi * m1.x;
    float p1 = qlo * m0.y + qhi * m1.y;
    float p2 = qlo * m0.z + qhi * m1.z;
    float p3 = qlo * m0.w + qhi * m1.w;
    #pragma unroll
    for (int mask = 4; mask <= 16; mask <<= 1) {
        p0 += __shfl_xor_sync(0xffffffffu, p0, mask);
        p1 += __shfl_xor_sync(0xffffffffu, p1, mask);
        p2 += __shfl_xor_sync(0xffffffffu, p2, mask);
        p3 += __shfl_xor_sync(0xffffffffu, p3, mask);
    }

    // C = sum_i Q[i]*Kf[i] + CST
    float c = 0.f;
    if (l < 16) c = g_Q[n * HC + hd * 16 + l] * kf;
    #pragma unroll
    for (int mask = 1; mask <= 16; mask <<= 1)
        c += __shfl_xor_sync(0xffffffffu, c, mask);
    c += CSTADD;

    if (l < 4) {
        // layerwise = softmax over heads of headwise[:, hop]
        float h0 = headwise[0 * KHOP + hop];
        float h1 = headwise[1 * KHOP + hop];
        float h2 = headwise[2 * KHOP + hop];
        float h3 = headwise[3 * KHOP + hop];
        float mx = fmaxf(fmaxf(h0, h1), fmaxf(h2, h3));
        float e0 = expf(h0 - mx), e1 = expf(h1 - mx), e2 = expf(h2 - mx), e3 = expf(h3 - mx);
        float denom = e0 + e1 + e2 + e3;
        float lw = ((hd == 0) ? e0 : (hd == 1) ? e1 : (hd == 2) ? e2 : e3) / denom;
        float gamma = hopwise[hop + 1] * lw;
        float sc = gamma / c;
        float4* hp = (float4*)(g_hid + n * HC + hd * 16 + l * 4);
        float4 hv = hp[0];
        hv.x += p0 * sc; hv.y += p1 * sc; hv.z += p2 * sc; hv.w += p3 * sc;
        hp[0] = hv;
    }
}

// ---------------- 8. output projection hidden[N,64] @ Wo[64,16] + bo ----------
__global__ void k_wo(const float* __restrict__ Wo, const float* __restrict__ bo,
                     float* __restrict__ out_hidden, int write_out) {
    int idx = blockIdx.x * blockDim.x + threadIdx.x;
    if (idx >= NN * 16) return;
    int n = idx >> 4, cc = idx & 15;
    float acc = bo[cc];
    #pragma unroll 8
    for (int k = 0; k < HC; k++) acc += g_hid[n * HC + k] * Wo[k * 16 + cc];
    g_hid16[idx] = acc;
    if (write_out) out_hidden[idx] = acc;
}

// ---------------- 9. edge regression head over FE edges ----------------
__global__ __launch_bounds__(256) void k_edge(
    const int* __restrict__ fei,
    const float* __restrict__ Wf1, const float* __restrict__ bf1,
    const float* __restrict__ Wf2, const float* __restrict__ bf2,
    float* __restrict__ out)
{
    __shared__ float w1[32 * 16];
    __shared__ float b1[16];
    __shared__ float w2[16];
    int t = threadIdx.x;
    for (int i = t; i < 512; i += 256) w1[i] = Wf1[i];
    if (t < 16) { b1[t] = bf1[t]; w2[t] = Wf2[t]; }
    __syncthreads();

    int e = blockIdx.x * blockDim.x + t;
    if (e >= FEE) return;
    int srow = fei[e];
    int drow = fei[FEE + e];

    float he[32];
    {
        const float4* hp = (const float4*)(g_hid16 + srow * 16);
        float4 v;
        v = hp[0]; he[0] = v.x; he[1] = v.y; he[2] = v.z; he[3] = v.w;
        v = hp[1]; he[4] = v.x; he[5] = v.y; he[6] = v.z; he[7] = v.w;
        v = hp[2]; he[8] = v.x; he[9] = v.y; he[10] = v.z; he[11] = v.w;
        v = hp[3]; he[12] = v.x; he[13] = v.y; he[14] = v.z; he[15] = v.w;
        const float4* hq = (const float4*)(g_hid16 + drow * 16);
        v = hq[0]; he[16] = v.x; he[17] = v.y; he[18] = v.z; he[19] = v.w;
        v = hq[1]; he[20] = v.x; he[21] = v.y; he[22] = v.z; he[23] = v.w;
        v = hq[2]; he[24] = v.x; he[25] = v.y; he[26] = v.z; he[27] = v.w;
        v = hq[3]; he[28] = v.x; he[29] = v.y; he[30] = v.z; he[31] = v.w;
    }

    float a[16];
    #pragma unroll
    for (int j = 0; j < 16; j++) a[j] = b1[j];
    #pragma unroll
    for (int k = 0; k < 32; k++) {
        float hv = he[k];
        const float4* wr = (const float4*)(w1 + k * 16);
        float4 w;
        w = wr[0]; a[0] += hv * w.x; a[1] += hv * w.y; a[2] += hv * w.z; a[3] += hv * w.w;
        w = wr[1]; a[4] += hv * w.x; a[5] += hv * w.y; a[6] += hv * w.z; a[7] += hv * w.w;
        w = wr[2]; a[8] += hv * w.x; a[9] += hv * w.y; a[10] += hv * w.z; a[11] += hv * w.w;
        w = wr[3]; a[12] += hv * w.x; a[13] += hv * w.y; a[14] += hv * w.z; a[15] += hv * w.w;
    }
    float outv = bf2[0];
    #pragma unroll
    for (int j = 0; j < 16; j++) outv += silu(a[j]) * w2[j];
    out[e] = outv;
}

// ---------------- launch ----------------
extern "C" void kernel_launch(void* const* d_in, const int* in_sizes, int n_in,
                              void* d_out, int out_size) {
    const float* x   = (const float*)d_in[0];
    const int* ei    = (const int*)d_in[1];
    const int* fei   = (const int*)d_in[2];
    const int* ts    = (const int*)d_in[3];
    const float* Wi  = (const float*)d_in[4];
    const float* bi  = (const float*)d_in[5];
    const float* Wt1 = (const float*)d_in[6];
    const float* bt1 = (const float*)d_in[7];
    const float* Wt2 = (const float*)d_in[8];
    const float* bt2 = (const float*)d_in[9];
    const float* WQ  = (const float*)d_in[10];
    const float* bQ  = (const float*)d_in[11];
    const float* WK  = (const float*)d_in[12];
    const float* bK  = (const float*)d_in[13];
    const float* WV  = (const float*)d_in[14];
    const float* bV  = (const float*)d_in[15];
    const float* Wo  = (const float*)d_in[16];
    const float* bo  = (const float*)d_in[17];
    const float* hopwise  = (const float*)d_in[18];
    const float* headwise = (const float*)d_in[19];
    const float* Wf1 = (const float*)d_in[20];
    const float* bf1 = (const float*)d_in[21];
    const float* Wf2 = (const float*)d_in[22];
    const float* bf2 = (const float*)d_in[23];
    float* out = (float*)d_out;

    // resolve scratch device pointers (host-side symbol addresses)
    static float* pM0 = nullptr;
    static float* pM1;
    static float* pK0;
    static float* pK1;
    if (!pM0) {
        cudaGetSymbolAddress((void**)&pM0, g_M);
        pM1 = pM0 + (size_t)NN * MSL;
        cudaGetSymbolAddress((void**)&pK0, g_Kf);
        pK1 = pK0 + (size_t)NN * HC;
    }

    int write_hidden = (out_size >= FEE + NN * 16) ? 1 : 0;
    float* out_hidden = out + FEE;

    k_zero<<<(NN + 255) / 256, 256>>>();
    k_deg<<<(EE + 255) / 256, 256>>>(ei);
    k_scan<<<1, 1024>>>();
    k_csr<<<(EE + 255) / 256, 256>>>(ei);
    k_temb<<<NUMT, 256>>>(Wt1, bt1, Wt2, bt2);
    k_feat<<<NN / 32, 256>>>(x, ts, Wi, bi, WQ, bQ, WK, bK, WV, bV, hopwise);

    // hops with ping-pong buffers
    k_hop<<<NN * HEADS / 8, 256>>>(pM0, pM1, pK0, pK1, hopwise, headwise, 0);
    k_hop<<<NN * HEADS / 8, 256>>>(pM1, pM0, pK1, pK0, hopwise, headwise, 1);
    k_hop<<<NN * HEADS / 8, 256>>>(pM0, pM1, pK0, pK1, hopwise, headwise, 2);

    k_wo<<<(NN * 16 + 255) / 256, 256>>>(Wo, bo, out_hidden, write_hidden);
    k_edge<<<(FEE + 255) / 256, 256>>>(fei, Wf1, bf1, Wf2, bf2, out);
}

// round 3
// speedup vs baseline: 1.1212x; 1.1212x over previous
#include <cuda_runtime.h>
#include <math.h>

// ---------------- problem constants ----------------
#define NN     20000
#define EE     160000
#define FEE    500000
#define HC     64
#define HEADS  4
#define HEADC  16
#define DV     16
#define KHOP   3
#define NUMT   128
#define CSTADD 1e-5f
#define MSL    1024   // HEADS*HEADC*DV floats of M per node

// ---------------- scratch (static device globals; no allocs) ----------------
__device__ float g_M[2][NN * MSL];      // ping-pong state matrices, 2 x 81.9MB
__device__ float g_Kf[2][NN * HC];
__device__ float g_Q[NN * HC];
__device__ float g_hid[NN * HC];        // per-head hidden accumulator [N,4,16]
__device__ float g_hid16[NN * 16];      // after Wo projection
__device__ float g_temb[NUMT * HC];     // timestep-embedding MLP table
__device__ int   g_deg[NN];
__device__ int   g_off[NN + 1];
__device__ int   g_cur[NN];
__device__ int   g_crow[EE];            // CSR (by dest): source node per edge
__device__ float g_cnorm[EE];           // edge weight (1/deg[row])

// ---------------- helpers ----------------
__device__ __forceinline__ float oneelu(float x) {
    return x > 0.f ? 1.f + x : expf(x);
}
__device__ __forceinline__ float silu(float x) {
    return x / (1.f + expf(-x));
}

// ---------------- 2. in-degree (over col) ----------------
__global__ void k_deg(const int* __restrict__ ei) {
    int e = blockIdx.x * blockDim.x + threadIdx.x;
    if (e < EE) atomicAdd(&g_deg[ei[EE + e]], 1);
}

// ---------------- 3. exclusive scan of deg -> off (single block) ----------------
__global__ void k_scan() {
    __shared__ int sums[1024];
    const int CH = 20;                       // 1024*20 = 20480 >= NN
    int t = threadIdx.x;
    int start = t * CH;
    int local[CH];
    int s = 0;
    #pragma unroll
    for (int i = 0; i < CH; i++) {
        int idx = start + i;
        int v = (idx < NN) ? g_deg[idx] : 0;
        local[i] = s;
        s += v;
    }
    sums[t] = s;
    __syncthreads();
    for (int d = 1; d < 1024; d <<= 1) {
        int v = (t >= d) ? sums[t - d] : 0;
        __syncthreads();
        sums[t] += v;
        __syncthreads();
    }
    int base = (t > 0) ? sums[t - 1] : 0;
    #pragma unroll
    for (int i = 0; i < CH; i++) {
        int idx = start + i;
        if (idx < NN) g_off[idx] = base + local[i];
    }
    if (t == 1023) g_off[NN] = sums[1023];
}

// ---------------- 4. fill CSR (+ per-edge norm) ----------------
__global__ void k_csr(const int* __restrict__ ei) {
    int e = blockIdx.x * blockDim.x + threadIdx.x;
    if (e >= EE) return;
    int r = ei[e];            // row (source)
    int c = ei[EE + e];       // col (dest)
    int pos = atomicAdd(&g_cur[c], 1);
    int idx = g_off[c] + pos;
    g_crow[idx] = r;
    int dr = g_deg[r];
    g_cnorm[idx] = (dr > 0) ? (1.f / (float)dr) : 0.f;
}

// ---------------- 5. timestep embedding MLP table (128 rows) ----------------
__global__ void k_temb(const float* __restrict__ Wt1, const float* __restrict__ bt1,
                       const float* __restrict__ Wt2, const float* __restrict__ bt2) {
    __shared__ float emb[HC];
    __shared__ float t1[4 * HC];
    int tb = blockIdx.x;                 // timestep value 0..127
    int t = threadIdx.x;                 // 256 threads
    if (t < 32) {
        float tt = (float)tb * (4000.0f / (float)NUMT);
        float f = expf(-logf(10000.0f) / 31.0f * (float)t);
        float a = tt * f;
        emb[t] = sinf(a);
        emb[32 + t] = cosf(a);
    }
    __syncthreads();
    {
        float acc = bt1[t];
        #pragma unroll 8
        for (int k = 0; k < HC; k++) acc += emb[k] * Wt1[k * 256 + t];
        t1[t] = silu(acc);
    }
    __syncthreads();
    if (t < HC) {
        float acc = bt2[t];
        #pragma unroll 8
        for (int k = 0; k < 256; k++) acc += t1[k] * Wt2[k * HC + t];
        g_temb[tb * HC + t] = acc;
    }
}

// ---------------- 6. per-node features: h, Q, K, V, M, hidden0 ----------------
__global__ __launch_bounds__(256) void k_feat(
    const float* __restrict__ x, const int* __restrict__ tsteps,
    const float* __restrict__ Wi, const float* __restrict__ bi,
    const float* __restrict__ WQ, const float* __restrict__ bQ,
    const float* __restrict__ WK, const float* __restrict__ bK,
    const float* __restrict__ WV, const float* __restrict__ bV,
    const float* __restrict__ hopwise)
{
    __shared__ float sh[8][1280];        // per warp: xs[512] hs[256] ks[256] vs[256]
    int wl = threadIdx.x >> 5, l = threadIdx.x & 31;
    float* xs = sh[wl];
    float* hs = xs + 512;
    float* ks = hs + 256;
    float* vs = ks + 256;
    int nb = (blockIdx.x * 8 + wl) * 4;  // first of 4 nodes
    float hw0 = hopwise[0];

    #pragma unroll
    for (int nn = 0; nn < 4; nn++) {
        int n = nb + nn;
        #pragma unroll
        for (int r = 0; r < 4; r++)
            xs[nn * 128 + l + 32 * r] = x[n * 128 + l + 32 * r];
    }
    __syncwarp();

    int c0 = l, c1 = l + 32;
    float a0[4], a1[4];
    #pragma unroll
    for (int nn = 0; nn < 4; nn++) {
        int n = nb + nn;
        int tt = tsteps[n];
        a0[nn] = bi[c0] + g_temb[tt * HC + c0];
        a1[nn] = bi[c1] + g_temb[tt * HC + c1];
    }
    #pragma unroll 4
    for (int k = 0; k < 128; k++) {
        float w0 = Wi[k * HC + c0];
        float w1 = Wi[k * HC + c1];
        #pragma unroll
        for (int nn = 0; nn < 4; nn++) {
            float xv = xs[nn * 128 + k];
            a0[nn] += xv * w0;
            a1[nn] += xv * w1;
        }
    }
    #pragma unroll
    for (int nn = 0; nn < 4; nn++) {
        hs[nn * 64 + c0] = fmaxf(a0[nn], 0.f);
        hs[nn * 64 + c1] = fmaxf(a1[nn], 0.f);
    }
    __syncwarp();

    float q0[4], q1[4], kk0[4], kk1[4], v0[4], v1[4];
    #pragma unroll
    for (int nn = 0; nn < 4; nn++) {
        q0[nn] = bQ[c0]; q1[nn] = bQ[c1];
        kk0[nn] = bK[c0]; kk1[nn] = bK[c1];
        v0[nn] = bV[c0]; v1[nn] = bV[c1];
    }
    #pragma unroll 4
    for (int k = 0; k < 64; k++) {
        float wq0 = WQ[k * HC + c0], wq1 = WQ[k * HC + c1];
        float wk0 = WK[k * HC + c0], wk1 = WK[k * HC + c1];
        float wv0 = WV[k * HC + c0], wv1 = WV[k * HC + c1];
        #pragma unroll
        for (int nn = 0; nn < 4; nn++) {
            float hv = hs[nn * 64 + k];
            q0[nn] += hv * wq0; q1[nn] += hv * wq1;
            kk0[nn] += hv * wk0; kk1[nn] += hv * wk1;
            v0[nn] += hv * wv0; v1[nn] += hv * wv1;
        }
    }
    #pragma unroll
    for (int nn = 0; nn < 4; nn++) {
        int n = nb + nn;
        float Qa = oneelu(q0[nn]), Qb = oneelu(q1[nn]);
        g_Q[n * HC + c0] = Qa; g_Q[n * HC + c1] = Qb;
        float Ka = oneelu(kk0[nn]), Kb = oneelu(kk1[nn]);
        g_Kf[0][n * HC + c0] = Ka; g_Kf[0][n * HC + c1] = Kb;
        ks[nn * 64 + c0] = Ka; ks[nn * 64 + c1] = Kb;
        vs[nn * 64 + c0] = v0[nn]; vs[nn * 64 + c1] = v1[nn];
        g_hid[n * HC + c0] = v0[nn] * hw0;
        g_hid[n * HC + c1] = v1[nn] * hw0;
    }
    __syncwarp();

    // M[n,h,i,j] = K[h,i] * V[h,j]  (flat f = h*256 + i*16 + j)
    #pragma unroll
    for (int nn = 0; nn < 4; nn++) {
        int n = nb + nn;
        float4* Mp = (float4*)(g_M[0] + (size_t)n * MSL);
        #pragma unroll
        for (int p = 0; p < 8; p++) {
            int f = p * 128 + l * 4;
            int hd = f >> 8;
            int rem = f & 255;
            int i = rem >> 4;
            int j = rem & 15;
            float kv = ks[nn * 64 + hd * 16 + i];
            float4 v4 = *(float4*)(vs + nn * 64 + hd * 16 + j);
            float4 m;
            m.x = kv * v4.x; m.y = kv * v4.y; m.z = kv * v4.z; m.w = kv * v4.w;
            Mp[p * 32 + l] = m;
        }
    }
}

// ---------------- 7. one propagation hop: warp per NODE (all 4 heads) -------
// Per edge: 8 independent float4 loads covering the full 4KB M row + 2 Kf loads.
__global__ __launch_bounds__(256) void k_hop(
    const float* __restrict__ Min, float* __restrict__ Mout,
    const float* __restrict__ Kin, float* __restrict__ Kout,
    const float* __restrict__ hopwise, const float* __restrict__ headwise,
    int hop)
{
    const unsigned F = 0xffffffffu;
    int n = blockIdx.x * 8 + (threadIdx.x >> 5);
    int l = threadIdx.x & 31;

    int s = g_off[n], e = g_off[n + 1];

    float4 m[8];
    #pragma unroll
    for (int p = 0; p < 8; p++) m[p] = make_float4(0.f, 0.f, 0.f, 0.f);
    float kfa = 0.f, kfb = 0.f;

    for (int k = s; k < e; k++) {
        int r = g_crow[k];
        float wt = g_cnorm[k];
        const float4* P = (const float4*)(Min + (size_t)r * MSL) + l;
        float4 a0 = P[0],   a1 = P[32],  a2 = P[64],  a3 = P[96];
        float4 a4 = P[128], a5 = P[160], a6 = P[192], a7 = P[224];
        float k0 = Kin[r * HC + l];
        float k1 = Kin[r * HC + 32 + l];
        m[0].x += wt * a0.x; m[0].y += wt * a0.y; m[0].z += wt * a0.z; m[0].w += wt * a0.w;
        m[1].x += wt * a1.x; m[1].y += wt * a1.y; m[1].z += wt * a1.z; m[1].w += wt * a1.w;
        m[2].x += wt * a2.x; m[2].y += wt * a2.y; m[2].z += wt * a2.z; m[2].w += wt * a2.w;
        m[3].x += wt * a3.x; m[3].y += wt * a3.y; m[3].z += wt * a3.z; m[3].w += wt * a3.w;
        m[4].x += wt * a4.x; m[4].y += wt * a4.y; m[4].z += wt * a4.z; m[4].w += wt * a4.w;
        m[5].x += wt * a5.x; m[5].y += wt * a5.y; m[5].z += wt * a5.z; m[5].w += wt * a5.w;
        m[6].x += wt * a6.x; m[6].y += wt * a6.y; m[6].z += wt * a6.z; m[6].w += wt * a6.w;
        m[7].x += wt * a7.x; m[7].y += wt * a7.y; m[7].z += wt * a7.z; m[7].w += wt * a7.w;
        kfa += wt * k0;
        kfb += wt * k1;
    }

    // streaming stores: outputs not re-read this kernel; keep input M in L2
    {
        float4* Qp = (float4*)(Mout + (size_t)n * MSL) + l;
        #pragma unroll
        for (int p = 0; p < 8; p++) __stcs(Qp + p * 32, m[p]);
        __stcs(Kout + n * HC + l, kfa);
        __stcs(Kout + n * HC + 32 + l, kfb);
    }

    // ---- epilogue: H = Q·M, C = Q·Kf, hidden += gamma/C * H -----------------
    float qa = g_Q[n * HC + l];
    float qb = g_Q[n * HC + 32 + l];

    // C per head: qa*kfa reduces within 16-lane halves -> heads 0,1; qb*kfb -> 2,3
    float t0 = qa * kfa, t1 = qb * kfb;
    #pragma unroll
    for (int mask = 1; mask <= 8; mask <<= 1) {
        t0 += __shfl_xor_sync(F, t0, mask);
        t1 += __shfl_xor_sync(F, t1, mask);
    }
    float cc[4];
    cc[0] = __shfl_sync(F, t0, 0)  + CSTADD;
    cc[1] = __shfl_sync(F, t0, 16) + CSTADD;
    cc[2] = __shfl_sync(F, t1, 0)  + CSTADD;
    cc[3] = __shfl_sync(F, t1, 16) + CSTADD;

    // gamma = hopwise[hop+1] * softmax(headwise[:,hop])
    float h0 = headwise[0 * KHOP + hop];
    float h1 = headwise[1 * KHOP + hop];
    float h2 = headwise[2 * KHOP + hop];
    float h3 = headwise[3 * KHOP + hop];
    float mx = fmaxf(fmaxf(h0, h1), fmaxf(h2, h3));
    float e0 = expf(h0 - mx), e1 = expf(h1 - mx), e2 = expf(h2 - mx), e3 = expf(h3 - mx);
    float denom = e0 + e1 + e2 + e3;
    float hw = hopwise[hop + 1] / denom;
    float sc[4];
    sc[0] = hw * e0 / cc[0];
    sc[1] = hw * e1 / cc[1];
    sc[2] = hw * e2 / cc[2];
    sc[3] = hw * e3 / cc[3];

    // H: for head hd, lane holds M rows i0=l>>2 (m[2hd]) and 8+i0 (m[2hd+1]),
    // columns j=(l&3)*4+comp. Butterfly over masks 4,8,16 sums all i.
    int i0 = l >> 2;
    float r0 = 0.f, r1 = 0.f, r2 = 0.f, r3 = 0.f, scsel = 0.f;
    #pragma unroll
    for (int hd = 0; hd < 4; hd++) {
        float src = (hd < 2) ? qa : qb;
        int base = (hd & 1) * 16;
        float qlo = __shfl_sync(F, src, base + i0);
        float qhi = __shfl_sync(F, src, base + 8 + i0);
        float4 A = m[2 * hd], B = m[2 * hd + 1];
        float p0 = qlo * A.x + qhi * B.x;
        float p1 = qlo * A.y + qhi * B.y;
        float p2 = qlo * A.z + qhi * B.z;
        float p3 = qlo * A.w + qhi * B.w;
        #pragma unroll
        for (int mask = 4; mask <= 16; mask <<= 1) {
            p0 += __shfl_xor_sync(F, p0, mask);
            p1 += __shfl_xor_sync(F, p1, mask);
            p2 += __shfl_xor_sync(F, p2, mask);
            p3 += __shfl_xor_sync(F, p3, mask);
        }
        if ((l >> 2) == hd) { r0 = p0; r1 = p1; r2 = p2; r3 = p3; scsel = sc[hd]; }
    }
    if (l < 16) {
        // float4 slot l == head (l>>2), j-group (l&3)
        float4* hp = (float4*)(g_hid + n * HC) + l;
        float4 hv = *hp;
        hv.x += r0 * scsel; hv.y += r1 * scsel; hv.z += r2 * scsel; hv.w += r3 * scsel;
        *hp = hv;
    }
}

// ---------------- 8. output projection hidden[N,64] @ Wo[64,16] + bo ----------
__global__ void k_wo(const float* __restrict__ Wo, const float* __restrict__ bo,
                     float* __restrict__ out_hidden, int write_out) {
    int idx = blockIdx.x * blockDim.x + threadIdx.x;
    if (idx >= NN * 16) return;
    int n = idx >> 4, cc = idx & 15;
    float acc = bo[cc];
    #pragma unroll 8
    for (int k = 0; k < HC; k++) acc += g_hid[n * HC + k] * Wo[k * 16 + cc];
    g_hid16[idx] = acc;
    if (write_out) out_hidden[idx] = acc;
}

// ---------------- 9. edge regression head over FE edges ----------------
__global__ __launch_bounds__(256) void k_edge(
    const int* __restrict__ fei,
    const float* __restrict__ Wf1, const float* __restrict__ bf1,
    const float* __restrict__ Wf2, const float* __restrict__ bf2,
    float* __restrict__ out)
{
    __shared__ float w1[32 * 16];
    __shared__ float b1[16];
    __shared__ float w2[16];
    int t = threadIdx.x;
    for (int i = t; i < 512; i += 256) w1[i] = Wf1[i];
    if (t < 16) { b1[t] = bf1[t]; w2[t] = Wf2[t]; }
    __syncthreads();

    int e = blockIdx.x * blockDim.x + t;
    if (e >= FEE) return;
    int srow = fei[e];
    int drow = fei[FEE + e];

    float he[32];
    {
        const float4* hp = (const float4*)(g_hid16 + srow * 16);
        float4 v;
        v = hp[0]; he[0] = v.x; he[1] = v.y; he[2] = v.z; he[3] = v.w;
        v = hp[1]; he[4] = v.x; he[5] = v.y; he[6] = v.z; he[7] = v.w;
        v = hp[2]; he[8] = v.x; he[9] = v.y; he[10] = v.z; he[11] = v.w;
        v = hp[3]; he[12] = v.x; he[13] = v.y; he[14] = v.z; he[15] = v.w;
        const float4* hq = (const float4*)(g_hid16 + drow * 16);
        v = hq[0]; he[16] = v.x; he[17] = v.y; he[18] = v.z; he[19] = v.w;
        v = hq[1]; he[20] = v.x; he[21] = v.y; he[22] = v.z; he[23] = v.w;
        v = hq[2]; he[24] = v.x; he[25] = v.y; he[26] = v.z; he[27] = v.w;
        v = hq[3]; he[28] = v.x; he[29] = v.y; he[30] = v.z; he[31] = v.w;
    }

    float a[16];
    #pragma unroll
    for (int j = 0; j < 16; j++) a[j] = b1[j];
    #pragma unroll
    for (int k = 0; k < 32; k++) {
        float hv = he[k];
        const float4* wr = (const float4*)(w1 + k * 16);
        float4 w;
        w = wr[0]; a[0] += hv * w.x; a[1] += hv * w.y; a[2] += hv * w.z; a[3] += hv * w.w;
        w = wr[1]; a[4] += hv * w.x; a[5] += hv * w.y; a[6] += hv * w.z; a[7] += hv * w.w;
        w = wr[2]; a[8] += hv * w.x; a[9] += hv * w.y; a[10] += hv * w.z; a[11] += hv * w.w;
        w = wr[3]; a[12] += hv * w.x; a[13] += hv * w.y; a[14] += hv * w.z; a[15] += hv * w.w;
    }
    float outv = bf2[0];
    #pragma unroll
    for (int j = 0; j < 16; j++) outv += silu(a[j]) * w2[j];
    out[e] = outv;
}

// ---------------- launch ----------------
extern "C" void kernel_launch(void* const* d_in, const int* in_sizes, int n_in,
                              void* d_out, int out_size) {
    const float* x   = (const float*)d_in[0];
    const int* ei    = (const int*)d_in[1];
    const int* fei   = (const int*)d_in[2];
    const int* ts    = (const int*)d_in[3];
    const float* Wi  = (const float*)d_in[4];
    const float* bi  = (const float*)d_in[5];
    const float* Wt1 = (const float*)d_in[6];
    const float* bt1 = (const float*)d_in[7];
    const float* Wt2 = (const float*)d_in[8];
    const float* bt2 = (const float*)d_in[9];
    const float* WQ  = (const float*)d_in[10];
    const float* bQ  = (const float*)d_in[11];
    const float* WK  = (const float*)d_in[12];
    const float* bK  = (const float*)d_in[13];
    const float* WV  = (const float*)d_in[14];
    const float* bV  = (const float*)d_in[15];
    const float* Wo  = (const float*)d_in[16];
    const float* bo  = (const float*)d_in[17];
    const float* hopwise  = (const float*)d_in[18];
    const float* headwise = (const float*)d_in[19];
    const float* Wf1 = (const float*)d_in[20];
    const float* bf1 = (const float*)d_in[21];
    const float* Wf2 = (const float*)d_in[22];
    const float* bf2 = (const float*)d_in[23];
    float* out = (float*)d_out;

    static float* pM0 = nullptr;
    static float* pM1;
    static float* pK0;
    static float* pK1;
    static int* pDeg;
    static int* pCur;
    if (!pM0) {
        cudaGetSymbolAddress((void**)&pM0, g_M);
        pM1 = pM0 + (size_t)NN * MSL;
        cudaGetSymbolAddress((void**)&pK0, g_Kf);
        pK1 = pK0 + (size_t)NN * HC;
        cudaGetSymbolAddress((void**)&pDeg, g_deg);
        cudaGetSymbolAddress((void**)&pCur, g_cur);
    }

    int write_hidden = (out_size >= FEE + NN * 16) ? 1 : 0;
    float* out_hidden = out + FEE;

    cudaMemsetAsync(pDeg, 0, NN * sizeof(int));
    cudaMemsetAsync(pCur, 0, NN * sizeof(int));

    k_deg<<<(EE + 255) / 256, 256>>>(ei);
    k_scan<<<1, 1024>>>();
    k_csr<<<(EE + 255) / 256, 256>>>(ei);
    k_temb<<<NUMT, 256>>>(Wt1, bt1, Wt2, bt2);
    k_feat<<<NN / 32, 256>>>(x, ts, Wi, bi, WQ, bQ, WK, bK, WV, bV, hopwise);

    // hops with ping-pong buffers (warp per node, all heads)
    k_hop<<<NN / 8, 256>>>(pM0, pM1, pK0, pK1, hopwise, headwise, 0);
    k_hop<<<NN / 8, 256>>>(pM1, pM0, pK1, pK0, hopwise, headwise, 1);
    k_hop<<<NN / 8, 256>>>(pM0, pM1, pK0, pK1, hopwise, headwise, 2);

    k_wo<<<(NN * 16 + 255) / 256, 256>>>(Wo, bo, out_hidden, write_hidden);
    k_edge<<<(FEE + 255) / 256, 256>>>(fei, Wf1, bf1, Wf2, bf2, out);
}